// round 9
// baseline (speedup 1.0000x reference)
#include <cuda_runtime.h>
#include <cuda_fp16.h>
#include <cstdint>

#define BDIM 8
#define NDIM 256
#define HDIM 128
#define INDIM 259
#define NODES (BDIM * NDIM)  // 2048

// ---------------- device scratch ----------------
__device__ float g_P[NODES * HDIM];                 // W1a @ x (per node, fp32)
__device__ __half g_Qh[NODES * HDIM];               // W1b @ x (per node, f16)
__device__ float g_b1eff[HDIM];                     // b1 + W1c @ bd
__device__ __half g_Wf[HDIM * HDIM];                // W1c @ Wd  [h][k], f16
__device__ __half g_W2h[HDIM * HDIM];               // W2        [g][h], f16
__device__ float g_W1aT[HDIM * HDIM];               // W1a^T [k][h]
__device__ float g_W1bT[HDIM * HDIM];               // W1b^T [k][h]
__device__ float g_part[2 * NODES * 3];             // per half-CTA partial sums
__device__ int   g_cnt[NODES];                      // arrival counters (zero-init)

// ---------------- helpers ----------------
__device__ __forceinline__ unsigned pack_h2(float lo, float hi) {
    unsigned r;
    asm("cvt.rn.f16x2.f32 %0, %1, %2;" : "=r"(r) : "f"(hi), "f"(lo));
    return r;
}
// packed silu over two fp32 inputs, result as f16x2 word
__device__ __forceinline__ unsigned silu2(float x0, float x1) {
    unsigned hx = pack_h2(x0, x1), hh, th, res;
    asm("mul.rn.f16x2 %0, %1, %2;" : "=r"(hh) : "r"(hx), "r"(0x38003800u)); // *0.5
    asm("tanh.approx.f16x2 %0, %1;" : "=r"(th) : "r"(hh));
    asm("fma.rn.f16x2 %0, %1, %2, %3;" : "=r"(res) : "r"(hh), "r"(th), "r"(hh));
    return res;
}
__device__ __forceinline__ uint32_t smem_u32(const void* p) {
    uint32_t a;
    asm("{ .reg .u64 t; cvta.to.shared.u64 t, %1; cvt.u32.u64 %0, t; }" : "=r"(a) : "l"(p));
    return a;
}

#define CP16(dst, src) \
    asm volatile("cp.async.cg.shared.global [%0], [%1], 16;" :: "r"(dst), "l"(src))
#define CP_COMMIT() asm volatile("cp.async.commit_group;")
#define CP_WAIT0()  asm volatile("cp.async.wait_group 0;")
#define BAR_GROUP(id) \
    asm volatile("bar.sync %0, 128;" :: "r"(id) : "memory")

// ---------------- prep_w: fused weights + W1 transpose (128 blocks) ----------------
__global__ __launch_bounds__(256)
void prep_w(const float* __restrict__ Wd, const float* __restrict__ bd,
            const float* __restrict__ W1, const float* __restrict__ b1,
            const float* __restrict__ W2) {
    int h = blockIdx.x;
    int t = threadIdx.x;
    if (t < 128) {
        int k = t;
        float w1c0 = W1[h * INDIM + 2 * HDIM + 0];
        float w1c1 = W1[h * INDIM + 2 * HDIM + 1];
        float w1c2 = W1[h * INDIM + 2 * HDIM + 2];
        float v = w1c0 * Wd[k] + w1c1 * Wd[HDIM + k] + w1c2 * Wd[2 * HDIM + k];
        g_Wf[h * HDIM + k]  = __float2half_rn(v);
        g_W2h[h * HDIM + k] = __float2half_rn(W2[h * HDIM + k]);
        g_W1aT[k * HDIM + h] = W1[h * INDIM + k];
        if (k == 0)
            g_b1eff[h] = b1[h] + w1c0 * bd[0] + w1c1 * bd[1] + w1c2 * bd[2];
    } else {
        int k = t - 128;
        g_W1bT[k * HDIM + h] = W1[h * INDIM + HDIM + k];
    }
}

// ---------------- prep_pq: per-node P/Q + out init (256 blocks x 256 thr) ----------------
__global__ __launch_bounds__(256)
void prep_pq(const float* __restrict__ x_emb, const float* __restrict__ pos,
             float* __restrict__ out) {
    __shared__ float xs[8][HDIM];
    int t = threadIdx.x;
    int r0 = blockIdx.x * 8;
    for (int idx = t; idx < 8 * HDIM; idx += 256)
        xs[idx >> 7][idx & 127] = x_emb[r0 * HDIM + idx];
    if (t < 24)                       // out pre-init (combine folded into main)
        out[r0 * 3 + t] = pos[r0 * 3 + t];
    __syncthreads();

    const int h = t & 127;
    const int n0 = (t >> 7) * 4;

    float p[4] = {0.f, 0.f, 0.f, 0.f};
    float q[4] = {0.f, 0.f, 0.f, 0.f};
#pragma unroll 4
    for (int k = 0; k < HDIM; k++) {
        float wa = g_W1aT[k * HDIM + h];
        float wb = g_W1bT[k * HDIM + h];
#pragma unroll
        for (int ii = 0; ii < 4; ii++) {
            float xv = xs[n0 + ii][k];
            p[ii] = fmaf(wa, xv, p[ii]);
            q[ii] = fmaf(wb, xv, q[ii]);
        }
    }
#pragma unroll
    for (int ii = 0; ii < 4; ii++) {
        g_P[(size_t)(r0 + n0 + ii) * HDIM + h]  = p[ii];
        g_Qh[(size_t)(r0 + n0 + ii) * HDIM + h] = __float2half_rn(q[ii]);
    }
}

// ---------------- main fused kernel ----------------
// One CTA per (b, i, half): grid 4096, M = 128 rows of j per CTA. fp16 MMA ops,
// fp32 accum. 16 warps in 4(wm) x 4(wn); wm-group barriers; 2 CTAs/SM.
// Last-arriving CTA of each (b,i) pair writes out = pos + partA + partB.

#define PA 136                 // smem pitch in f16 (128 + 8 pad)
#define ROWB (PA * 2)          // 272 bytes per row

#define OFF_AS   0             // 128*272 = 34816 (A tile, reused for H1)
#define OFF_B1   34816         // 34816 (Wfuse)
#define OFF_B2   69632         // 34816 (W2)
#define OFF_BIAS 104448        // float[128]  P[i] + b1eff
#define OFF_W3   104960        // float[128]
#define OFF_B2V  105472        // float[128]
#define OFF_SRED 105984        // float[4*128] per-wn slices
#define OFF_RED3 108032        // float[4*3] pad
#define SMEM_TOTAL 108096

#define LDSM_X4(r0, r1, r2, r3, addr) \
    asm volatile("ldmatrix.sync.aligned.m8n8.x4.shared.b16 {%0,%1,%2,%3}, [%4];" \
                 : "=r"(r0), "=r"(r1), "=r"(r2), "=r"(r3) : "r"(addr))

__device__ __forceinline__ void do_gemm(uint32_t aLane, uint32_t bLane,
                                        float acc[2][4][4]) {
#pragma unroll
    for (int ks = 0; ks < 8; ks++) {
        uint32_t a[2][4], b[4][2];
#pragma unroll
        for (int mt = 0; mt < 2; mt++)
            LDSM_X4(a[mt][0], a[mt][1], a[mt][2], a[mt][3],
                    aLane + mt * (16 * ROWB) + ks * 32);
#pragma unroll
        for (int np = 0; np < 2; np++)
            LDSM_X4(b[2 * np][0], b[2 * np][1], b[2 * np + 1][0], b[2 * np + 1][1],
                    bLane + np * (16 * ROWB) + ks * 32);
#pragma unroll
        for (int mt = 0; mt < 2; mt++)
#pragma unroll
            for (int nt = 0; nt < 4; nt++)
                asm volatile(
                    "mma.sync.aligned.m16n8k16.row.col.f32.f16.f16.f32 "
                    "{%0,%1,%2,%3}, {%4,%5,%6,%7}, {%8,%9}, {%0,%1,%2,%3};\n"
                    : "+f"(acc[mt][nt][0]), "+f"(acc[mt][nt][1]),
                      "+f"(acc[mt][nt][2]), "+f"(acc[mt][nt][3])
                    : "r"(a[mt][0]), "r"(a[mt][1]), "r"(a[mt][2]), "r"(a[mt][3]),
                      "r"(b[nt][0]), "r"(b[nt][1]));
    }
}

__global__ __launch_bounds__(512, 2)
void pos_update_main(const float* __restrict__ pair_emb,
                     const float* __restrict__ coord_diff,
                     const float* __restrict__ pair_mask,
                     const float* __restrict__ b2,
                     const float* __restrict__ W3,
                     const float* __restrict__ pos,
                     float* __restrict__ out) {
    extern __shared__ char smem[];
    __half* As   = reinterpret_cast<__half*>(smem + OFF_AS);
    float* biasI = reinterpret_cast<float*>(smem + OFF_BIAS);
    float* w3s   = reinterpret_cast<float*>(smem + OFF_W3);
    float* b2s   = reinterpret_cast<float*>(smem + OFF_B2V);
    float* sRedW = reinterpret_cast<float*>(smem + OFF_SRED);   // [4][128]
    float* red3  = reinterpret_cast<float*>(smem + OFF_RED3);
    __shared__ int amLast;

    const uint32_t sb = smem_u32(smem);
    const int tid  = threadIdx.x;
    const int lane = tid & 31;
    const int warp = tid >> 5;
    const int wm = warp >> 2, wn = warp & 3;
    const int g = lane >> 2, l4 = lane & 3;
    const int blk2 = blockIdx.x;              // (b*256+i)*2 + half
    const int blk  = blk2 >> 1;               // b*256 + i
    const int j0   = (blk2 & 1) << 7;         // 0 or 128
    const int bbase = blk & ~255;             // b*256

    const uint32_t aLane = sb + OFF_AS + (uint32_t)(wm * 32 + (lane & 15)) * ROWB
                              + (uint32_t)(lane >> 4) * 16;
    const uint32_t bLane1 = sb + OFF_B1
        + (uint32_t)(wn * 32 + (lane & 7) + ((lane >> 4) << 3)) * ROWB
        + (uint32_t)((lane >> 3) & 1) * 16;
    const uint32_t bLane2 = bLane1 + (OFF_B2 - OFF_B1);

    // ---- load phase ----
    {
        const char* w1 = reinterpret_cast<const char*>(g_Wf);
        const char* w2 = reinterpret_cast<const char*>(g_W2h);
#pragma unroll
        for (int it = 0; it < 4; it++) {
            int idx = tid + it * 512;         // 2048 x 16B
            int r = idx >> 4, c = (idx & 15) << 3;
            uint32_t doff = (uint32_t)(r * PA + c) * 2;
            CP16(sb + OFF_B1 + doff, w1 + idx * 16);
            CP16(sb + OFF_B2 + doff, w2 + idx * 16);
        }
        CP_COMMIT();

        const float4* src = reinterpret_cast<const float4*>(
            pair_emb + ((size_t)blk * NDIM + j0) * HDIM);
#pragma unroll
        for (int it = 0; it < 8; it++) {
            int idx = tid + it * 512;         // 4096 float4
            float4 f = src[idx];
            int r = idx >> 5, c = (idx & 31) << 2;
            uint2 v; v.x = pack_h2(f.x, f.y); v.y = pack_h2(f.z, f.w);
            *reinterpret_cast<uint2*>(As + r * PA + c) = v;
        }
        if (tid < 128) {
            biasI[tid] = g_P[(size_t)blk * HDIM + tid] + g_b1eff[tid];
            w3s[tid] = W3[tid];
            b2s[tid] = b2[tid];
        }
        CP_WAIT0();
    }
    __syncthreads();

    float acc[2][4][4];

    // ---- GEMM1 ----
#pragma unroll
    for (int mt = 0; mt < 2; mt++)
#pragma unroll
        for (int nt = 0; nt < 4; nt++)
#pragma unroll
            for (int e = 0; e < 4; e++) acc[mt][nt][e] = 0.f;

    do_gemm(aLane, bLane1, acc);

    // wm-group barrier: all 4 warps of this row-group finish A-reads first
    BAR_GROUP(1 + wm);

    // ---- epilogue 1: silu(acc + biasI + Q[j]) -> H1 f16 into As ----
#pragma unroll
    for (int mt = 0; mt < 2; mt++) {
        int r = wm * 32 + mt * 16 + g;
        const __half* qrow = g_Qh + (size_t)(bbase + j0 + r) * HDIM;
#pragma unroll
        for (int nt = 0; nt < 4; nt++) {
            int c = wn * 32 + nt * 8 + l4 * 2;
            float2 ql = __half22float2(*reinterpret_cast<const __half2*>(qrow + c));
            float2 qh = __half22float2(*reinterpret_cast<const __half2*>(qrow + 8 * HDIM + c));
            float bc0 = biasI[c], bc1 = biasI[c + 1];
            float x0 = acc[mt][nt][0] + bc0 + ql.x;
            float x1 = acc[mt][nt][1] + bc1 + ql.y;
            float x2 = acc[mt][nt][2] + bc0 + qh.x;
            float x3 = acc[mt][nt][3] + bc1 + qh.y;
            *reinterpret_cast<unsigned*>(As + r * PA + c)       = silu2(x0, x1);
            *reinterpret_cast<unsigned*>(As + (r + 8) * PA + c) = silu2(x2, x3);
        }
    }

    // wm-group barrier: all column slices of H1 written before GEMM2 reads
    BAR_GROUP(1 + wm);

    // ---- GEMM2 ----
#pragma unroll
    for (int mt = 0; mt < 2; mt++)
#pragma unroll
        for (int nt = 0; nt < 4; nt++)
#pragma unroll
            for (int e = 0; e < 4; e++) acc[mt][nt][e] = 0.f;

    do_gemm(aLane, bLane2, acc);

    // ---- epilogue 2: silu (packed), dot with W3, per-wn slice write ----
    float sAcc[2][2];
#pragma unroll
    for (int mt = 0; mt < 2; mt++) { sAcc[mt][0] = 0.f; sAcc[mt][1] = 0.f; }
#pragma unroll
    for (int mt = 0; mt < 2; mt++) {
#pragma unroll
        for (int nt = 0; nt < 4; nt++) {
            int c = wn * 32 + nt * 8 + l4 * 2;
            float bb0 = b2s[c], bb1 = b2s[c + 1];
            float w30 = w3s[c], w31 = w3s[c + 1];
            unsigned ylo = silu2(acc[mt][nt][0] + bb0, acc[mt][nt][1] + bb1);
            unsigned yhi = silu2(acc[mt][nt][2] + bb0, acc[mt][nt][3] + bb1);
            float2 y01 = __half22float2(*reinterpret_cast<__half2*>(&ylo));
            float2 y23 = __half22float2(*reinterpret_cast<__half2*>(&yhi));
            sAcc[mt][0] += y01.x * w30 + y01.y * w31;
            sAcc[mt][1] += y23.x * w30 + y23.y * w31;
        }
    }
#pragma unroll
    for (int mt = 0; mt < 2; mt++) {
#pragma unroll
        for (int hh = 0; hh < 2; hh++) {
            sAcc[mt][hh] += __shfl_xor_sync(0xffffffffu, sAcc[mt][hh], 1);
            sAcc[mt][hh] += __shfl_xor_sync(0xffffffffu, sAcc[mt][hh], 2);
        }
    }
    if (l4 == 0) {
#pragma unroll
        for (int mt = 0; mt < 2; mt++) {
            sRedW[wn * 128 + wm * 32 + mt * 16 + g]     = sAcc[mt][0];
            sRedW[wn * 128 + wm * 32 + mt * 16 + 8 + g] = sAcc[mt][1];
        }
    }
    __syncthreads();

    // ---- partial trans sum over this CTA's 128 j's ----
    float t0 = 0.f, t1 = 0.f, t2 = 0.f;
    if (tid < 128) {
        size_t jj = (size_t)blk * NDIM + j0 + tid;
        float s = sRedW[tid] + sRedW[128 + tid] + sRedW[256 + tid] + sRedW[384 + tid];
        float sj = s * pair_mask[jj];
        const float* cd = coord_diff + jj * 3;
        t0 = cd[0] * sj; t1 = cd[1] * sj; t2 = cd[2] * sj;
    }
#pragma unroll
    for (int off = 16; off > 0; off >>= 1) {
        t0 += __shfl_down_sync(0xffffffffu, t0, off);
        t1 += __shfl_down_sync(0xffffffffu, t1, off);
        t2 += __shfl_down_sync(0xffffffffu, t2, off);
    }
    if (warp < 4 && lane == 0) {
        red3[warp * 3 + 0] = t0;
        red3[warp * 3 + 1] = t1;
        red3[warp * 3 + 2] = t2;
    }
    __syncthreads();

    // ---- publish partial; last-arriving CTA of the pair writes out ----
    if (tid < 3) {
        float s = red3[tid] + red3[3 + tid] + red3[6 + tid] + red3[9 + tid];
        g_part[(size_t)blk2 * 3 + tid] = s;
    }
    __threadfence();
    if (tid == 0) {
        int prev = atomicAdd(&g_cnt[blk], 1);
        amLast = (prev == 1) ? 1 : 0;
    }
    __syncthreads();
    if (amLast) {
        if (tid == 0) g_cnt[blk] = 0;       // reset for next graph replay
        if (tid < 3) {
            float pA = g_part[(size_t)(blk * 2) * 3 + tid];
            float pB = g_part[(size_t)(blk * 2 + 1) * 3 + tid];
            out[blk * 3 + tid] = pos[blk * 3 + tid] + (pA + pB);
        }
    }
}

// ---------------- launcher ----------------
extern "C" void kernel_launch(void* const* d_in, const int* in_sizes, int n_in,
                              void* d_out, int out_size) {
    const float* x_emb      = (const float*)d_in[0];
    const float* pair_emb   = (const float*)d_in[1];
    const float* pos        = (const float*)d_in[2];
    const float* coord_diff = (const float*)d_in[3];
    const float* pair_mask  = (const float*)d_in[5];
    const float* Wd         = (const float*)d_in[6];
    const float* bd         = (const float*)d_in[7];
    const float* W1         = (const float*)d_in[8];
    const float* b1         = (const float*)d_in[9];
    const float* W2         = (const float*)d_in[10];
    const float* b2         = (const float*)d_in[11];
    const float* W3         = (const float*)d_in[12];
    float* out = (float*)d_out;

    cudaFuncSetAttribute(pos_update_main,
                         cudaFuncAttributeMaxDynamicSharedMemorySize, SMEM_TOTAL);

    prep_w<<<128, 256>>>(Wd, bd, W1, b1, W2);
    prep_pq<<<256, 256>>>(x_emb, pos, out);
    pos_update_main<<<2 * NODES, 512, SMEM_TOTAL>>>(pair_emb, coord_diff,
                                                    pair_mask, b2, W3, pos, out);
    (void)in_sizes; (void)n_in; (void)out_size;
}

// round 10
// speedup vs baseline: 1.0922x; 1.0922x over previous
#include <cuda_runtime.h>
#include <cuda_fp16.h>
#include <cstdint>

#define BDIM 8
#define NDIM 256
#define HDIM 128
#define INDIM 259
#define NODES (BDIM * NDIM)  // 2048

// ---------------- device scratch ----------------
__device__ float g_P[NODES * HDIM];                 // W1a @ x (per node, fp32)
__device__ __half g_Qh[NODES * HDIM];               // W1b @ x (per node, f16)
__device__ float g_b1eff[HDIM];                     // b1 + W1c @ bd
__device__ __half g_Wf[HDIM * HDIM];                // W1c @ Wd  [h][k], f16
__device__ __half g_W2h[HDIM * HDIM];               // W2        [g][h], f16
__device__ float g_W1aT[HDIM * HDIM];               // W1a^T [k][h]
__device__ float g_W1bT[HDIM * HDIM];               // W1b^T [k][h]
__device__ float g_part[2 * NODES * 3];             // per half-CTA partial sums

// ---------------- helpers ----------------
__device__ __forceinline__ unsigned pack_h2(float lo, float hi) {
    unsigned r;
    asm("cvt.rn.f16x2.f32 %0, %1, %2;" : "=r"(r) : "f"(hi), "f"(lo));
    return r;
}
// packed silu over two fp32 inputs, result as f16x2 word
__device__ __forceinline__ unsigned silu2(float x0, float x1) {
    unsigned hx = pack_h2(x0, x1), hh, th, res;
    asm("mul.rn.f16x2 %0, %1, %2;" : "=r"(hh) : "r"(hx), "r"(0x38003800u)); // *0.5
    asm("tanh.approx.f16x2 %0, %1;" : "=r"(th) : "r"(hh));
    asm("fma.rn.f16x2 %0, %1, %2, %3;" : "=r"(res) : "r"(hh), "r"(th), "r"(hh));
    return res;
}
__device__ __forceinline__ uint32_t smem_u32(const void* p) {
    uint32_t a;
    asm("{ .reg .u64 t; cvta.to.shared.u64 t, %1; cvt.u32.u64 %0, t; }" : "=r"(a) : "l"(p));
    return a;
}

#define CP16(dst, src) \
    asm volatile("cp.async.cg.shared.global [%0], [%1], 16;" :: "r"(dst), "l"(src))
#define CP_COMMIT() asm volatile("cp.async.commit_group;")
#define CP_WAIT0()  asm volatile("cp.async.wait_group 0;")
#define BAR_GROUP(id) \
    asm volatile("bar.sync %0, 128;" :: "r"(id) : "memory")

// ---------------- prep_w: fused weights + W1 transpose (128 blocks) ----------------
__global__ __launch_bounds__(256)
void prep_w(const float* __restrict__ Wd, const float* __restrict__ bd,
            const float* __restrict__ W1, const float* __restrict__ b1,
            const float* __restrict__ W2) {
    int h = blockIdx.x;
    int t = threadIdx.x;
    if (t < 128) {
        int k = t;
        float w1c0 = W1[h * INDIM + 2 * HDIM + 0];
        float w1c1 = W1[h * INDIM + 2 * HDIM + 1];
        float w1c2 = W1[h * INDIM + 2 * HDIM + 2];
        float v = w1c0 * Wd[k] + w1c1 * Wd[HDIM + k] + w1c2 * Wd[2 * HDIM + k];
        g_Wf[h * HDIM + k]  = __float2half_rn(v);
        g_W2h[h * HDIM + k] = __float2half_rn(W2[h * HDIM + k]);
        g_W1aT[k * HDIM + h] = W1[h * INDIM + k];
        if (k == 0)
            g_b1eff[h] = b1[h] + w1c0 * bd[0] + w1c1 * bd[1] + w1c2 * bd[2];
    } else {
        int k = t - 128;
        g_W1bT[k * HDIM + h] = W1[h * INDIM + HDIM + k];
    }
}

// ---------------- prep_pq: per-node P/Q (256 blocks x 256 thr, coalesced) ----------------
__global__ __launch_bounds__(256)
void prep_pq(const float* __restrict__ x_emb) {
    __shared__ float xs[8][HDIM];
    int t = threadIdx.x;
    int r0 = blockIdx.x * 8;
    for (int idx = t; idx < 8 * HDIM; idx += 256)
        xs[idx >> 7][idx & 127] = x_emb[r0 * HDIM + idx];
    __syncthreads();

    const int h = t & 127;
    const int n0 = (t >> 7) * 4;

    float p[4] = {0.f, 0.f, 0.f, 0.f};
    float q[4] = {0.f, 0.f, 0.f, 0.f};
#pragma unroll 4
    for (int k = 0; k < HDIM; k++) {
        float wa = g_W1aT[k * HDIM + h];
        float wb = g_W1bT[k * HDIM + h];
#pragma unroll
        for (int ii = 0; ii < 4; ii++) {
            float xv = xs[n0 + ii][k];
            p[ii] = fmaf(wa, xv, p[ii]);
            q[ii] = fmaf(wb, xv, q[ii]);
        }
    }
#pragma unroll
    for (int ii = 0; ii < 4; ii++) {
        g_P[(size_t)(r0 + n0 + ii) * HDIM + h]  = p[ii];
        g_Qh[(size_t)(r0 + n0 + ii) * HDIM + h] = __float2half_rn(q[ii]);
    }
}

// ---------------- main fused kernel ----------------
// One CTA per (b, i, half): grid 4096, M = 128 rows of j per CTA. fp16 MMA ops,
// fp32 accum. 16 warps in 4(wm) x 4(wn); wm-group barriers; 2 CTAs/SM.

#define PA 136                 // smem pitch in f16 (128 + 8 pad)
#define ROWB (PA * 2)          // 272 bytes per row

#define OFF_AS   0             // 128*272 = 34816 (A tile, reused for H1)
#define OFF_B1   34816         // 34816 (Wfuse)
#define OFF_B2   69632         // 34816 (W2)
#define OFF_BIAS 104448        // float[128]  P[i] + b1eff
#define OFF_W3   104960        // float[128]
#define OFF_B2V  105472        // float[128]
#define OFF_SRED 105984        // float[4*128] per-wn slices
#define OFF_RED3 108032        // float[4*3] pad
#define SMEM_TOTAL 108096

#define LDSM_X4(r0, r1, r2, r3, addr) \
    asm volatile("ldmatrix.sync.aligned.m8n8.x4.shared.b16 {%0,%1,%2,%3}, [%4];" \
                 : "=r"(r0), "=r"(r1), "=r"(r2), "=r"(r3) : "r"(addr))

__device__ __forceinline__ void do_gemm(uint32_t aLane, uint32_t bLane,
                                        float acc[2][4][4]) {
#pragma unroll
    for (int ks = 0; ks < 8; ks++) {
        uint32_t a[2][4], b[4][2];
#pragma unroll
        for (int mt = 0; mt < 2; mt++)
            LDSM_X4(a[mt][0], a[mt][1], a[mt][2], a[mt][3],
                    aLane + mt * (16 * ROWB) + ks * 32);
#pragma unroll
        for (int np = 0; np < 2; np++)
            LDSM_X4(b[2 * np][0], b[2 * np][1], b[2 * np + 1][0], b[2 * np + 1][1],
                    bLane + np * (16 * ROWB) + ks * 32);
#pragma unroll
        for (int mt = 0; mt < 2; mt++)
#pragma unroll
            for (int nt = 0; nt < 4; nt++)
                asm volatile(
                    "mma.sync.aligned.m16n8k16.row.col.f32.f16.f16.f32 "
                    "{%0,%1,%2,%3}, {%4,%5,%6,%7}, {%8,%9}, {%0,%1,%2,%3};\n"
                    : "+f"(acc[mt][nt][0]), "+f"(acc[mt][nt][1]),
                      "+f"(acc[mt][nt][2]), "+f"(acc[mt][nt][3])
                    : "r"(a[mt][0]), "r"(a[mt][1]), "r"(a[mt][2]), "r"(a[mt][3]),
                      "r"(b[nt][0]), "r"(b[nt][1]));
    }
}

__global__ __launch_bounds__(512, 2)
void pos_update_main(const float* __restrict__ pair_emb,
                     const float* __restrict__ coord_diff,
                     const float* __restrict__ pair_mask,
                     const float* __restrict__ b2,
                     const float* __restrict__ W3) {
    extern __shared__ char smem[];
    __half* As   = reinterpret_cast<__half*>(smem + OFF_AS);
    float* biasI = reinterpret_cast<float*>(smem + OFF_BIAS);
    float* w3s   = reinterpret_cast<float*>(smem + OFF_W3);
    float* b2s   = reinterpret_cast<float*>(smem + OFF_B2V);
    float* sRedW = reinterpret_cast<float*>(smem + OFF_SRED);   // [4][128]
    float* red3  = reinterpret_cast<float*>(smem + OFF_RED3);

    const uint32_t sb = smem_u32(smem);
    const int tid  = threadIdx.x;
    const int lane = tid & 31;
    const int warp = tid >> 5;
    const int wm = warp >> 2, wn = warp & 3;
    const int g = lane >> 2, l4 = lane & 3;
    const int blk2 = blockIdx.x;              // (b*256+i)*2 + half
    const int blk  = blk2 >> 1;               // b*256 + i
    const int j0   = (blk2 & 1) << 7;         // 0 or 128
    const int bbase = blk & ~255;             // b*256

    const uint32_t aLane = sb + OFF_AS + (uint32_t)(wm * 32 + (lane & 15)) * ROWB
                              + (uint32_t)(lane >> 4) * 16;
    const uint32_t bLane1 = sb + OFF_B1
        + (uint32_t)(wn * 32 + (lane & 7) + ((lane >> 4) << 3)) * ROWB
        + (uint32_t)((lane >> 3) & 1) * 16;
    const uint32_t bLane2 = bLane1 + (OFF_B2 - OFF_B1);

    // ---- load phase ----
    {
        const char* w1 = reinterpret_cast<const char*>(g_Wf);
        const char* w2 = reinterpret_cast<const char*>(g_W2h);
#pragma unroll
        for (int it = 0; it < 4; it++) {
            int idx = tid + it * 512;         // 2048 x 16B
            int r = idx >> 4, c = (idx & 15) << 3;
            uint32_t doff = (uint32_t)(r * PA + c) * 2;
            CP16(sb + OFF_B1 + doff, w1 + idx * 16);
            CP16(sb + OFF_B2 + doff, w2 + idx * 16);
        }
        CP_COMMIT();

        const float4* src = reinterpret_cast<const float4*>(
            pair_emb + ((size_t)blk * NDIM + j0) * HDIM);
#pragma unroll
        for (int it = 0; it < 8; it++) {
            int idx = tid + it * 512;         // 4096 float4
            float4 f = src[idx];
            int r = idx >> 5, c = (idx & 31) << 2;
            uint2 v; v.x = pack_h2(f.x, f.y); v.y = pack_h2(f.z, f.w);
            *reinterpret_cast<uint2*>(As + r * PA + c) = v;
        }
        if (tid < 128) {
            biasI[tid] = g_P[(size_t)blk * HDIM + tid] + g_b1eff[tid];
            w3s[tid] = W3[tid];
            b2s[tid] = b2[tid];
        }
        CP_WAIT0();
    }
    __syncthreads();

    float acc[2][4][4];

    // ---- GEMM1 ----
#pragma unroll
    for (int mt = 0; mt < 2; mt++)
#pragma unroll
        for (int nt = 0; nt < 4; nt++)
#pragma unroll
            for (int e = 0; e < 4; e++) acc[mt][nt][e] = 0.f;

    do_gemm(aLane, bLane1, acc);

    // wm-group barrier: all 4 warps of this row-group finish A-reads first
    BAR_GROUP(1 + wm);

    // ---- epilogue 1: silu(acc + biasI + Q[j]) -> H1 f16 into As ----
#pragma unroll
    for (int mt = 0; mt < 2; mt++) {
        int r = wm * 32 + mt * 16 + g;
        const __half* qrow = g_Qh + (size_t)(bbase + j0 + r) * HDIM;
#pragma unroll
        for (int nt = 0; nt < 4; nt++) {
            int c = wn * 32 + nt * 8 + l4 * 2;
            float2 ql = __half22float2(*reinterpret_cast<const __half2*>(qrow + c));
            float2 qh = __half22float2(*reinterpret_cast<const __half2*>(qrow + 8 * HDIM + c));
            float bc0 = biasI[c], bc1 = biasI[c + 1];
            float x0 = acc[mt][nt][0] + bc0 + ql.x;
            float x1 = acc[mt][nt][1] + bc1 + ql.y;
            float x2 = acc[mt][nt][2] + bc0 + qh.x;
            float x3 = acc[mt][nt][3] + bc1 + qh.y;
            *reinterpret_cast<unsigned*>(As + r * PA + c)       = silu2(x0, x1);
            *reinterpret_cast<unsigned*>(As + (r + 8) * PA + c) = silu2(x2, x3);
        }
    }

    // wm-group barrier: all column slices of H1 written before GEMM2 reads
    BAR_GROUP(1 + wm);

    // ---- GEMM2 ----
#pragma unroll
    for (int mt = 0; mt < 2; mt++)
#pragma unroll
        for (int nt = 0; nt < 4; nt++)
#pragma unroll
            for (int e = 0; e < 4; e++) acc[mt][nt][e] = 0.f;

    do_gemm(aLane, bLane2, acc);

    // ---- epilogue 2: silu (packed), dot with W3, per-wn slice write ----
    float sAcc[2][2];
#pragma unroll
    for (int mt = 0; mt < 2; mt++) { sAcc[mt][0] = 0.f; sAcc[mt][1] = 0.f; }
#pragma unroll
    for (int mt = 0; mt < 2; mt++) {
#pragma unroll
        for (int nt = 0; nt < 4; nt++) {
            int c = wn * 32 + nt * 8 + l4 * 2;
            float bb0 = b2s[c], bb1 = b2s[c + 1];
            float w30 = w3s[c], w31 = w3s[c + 1];
            unsigned ylo = silu2(acc[mt][nt][0] + bb0, acc[mt][nt][1] + bb1);
            unsigned yhi = silu2(acc[mt][nt][2] + bb0, acc[mt][nt][3] + bb1);
            float2 y01 = __half22float2(*reinterpret_cast<__half2*>(&ylo));
            float2 y23 = __half22float2(*reinterpret_cast<__half2*>(&yhi));
            sAcc[mt][0] += y01.x * w30 + y01.y * w31;
            sAcc[mt][1] += y23.x * w30 + y23.y * w31;
        }
    }
#pragma unroll
    for (int mt = 0; mt < 2; mt++) {
#pragma unroll
        for (int hh = 0; hh < 2; hh++) {
            sAcc[mt][hh] += __shfl_xor_sync(0xffffffffu, sAcc[mt][hh], 1);
            sAcc[mt][hh] += __shfl_xor_sync(0xffffffffu, sAcc[mt][hh], 2);
        }
    }
    if (l4 == 0) {
#pragma unroll
        for (int mt = 0; mt < 2; mt++) {
            sRedW[wn * 128 + wm * 32 + mt * 16 + g]     = sAcc[mt][0];
            sRedW[wn * 128 + wm * 32 + mt * 16 + 8 + g] = sAcc[mt][1];
        }
    }
    __syncthreads();

    // ---- partial trans sum over this CTA's 128 j's ----
    float t0 = 0.f, t1 = 0.f, t2 = 0.f;
    if (tid < 128) {
        size_t jj = (size_t)blk * NDIM + j0 + tid;
        float s = sRedW[tid] + sRedW[128 + tid] + sRedW[256 + tid] + sRedW[384 + tid];
        float sj = s * pair_mask[jj];
        const float* cd = coord_diff + jj * 3;
        t0 = cd[0] * sj; t1 = cd[1] * sj; t2 = cd[2] * sj;
    }
#pragma unroll
    for (int off = 16; off > 0; off >>= 1) {
        t0 += __shfl_down_sync(0xffffffffu, t0, off);
        t1 += __shfl_down_sync(0xffffffffu, t1, off);
        t2 += __shfl_down_sync(0xffffffffu, t2, off);
    }
    if (warp < 4 && lane == 0) {
        red3[warp * 3 + 0] = t0;
        red3[warp * 3 + 1] = t1;
        red3[warp * 3 + 2] = t2;
    }
    __syncthreads();
    if (tid < 3) {
        float s = red3[tid] + red3[3 + tid] + red3[6 + tid] + red3[9 + tid];
        g_part[(size_t)blk2 * 3 + tid] = s;
    }
}

// ---------------- combine kernel ----------------
__global__ void combine(const float* __restrict__ pos, float* __restrict__ out) {
    int i = blockIdx.x * blockDim.x + threadIdx.x;   // 0..6143
    if (i < NODES * 3) {
        int blk = i / 3, d = i - blk * 3;
        out[i] = pos[i] + g_part[blk * 6 + d] + g_part[blk * 6 + 3 + d];
    }
}

// ---------------- launcher ----------------
extern "C" void kernel_launch(void* const* d_in, const int* in_sizes, int n_in,
                              void* d_out, int out_size) {
    const float* x_emb      = (const float*)d_in[0];
    const float* pair_emb   = (const float*)d_in[1];
    const float* pos        = (const float*)d_in[2];
    const float* coord_diff = (const float*)d_in[3];
    const float* pair_mask  = (const float*)d_in[5];
    const float* Wd         = (const float*)d_in[6];
    const float* bd         = (const float*)d_in[7];
    const float* W1         = (const float*)d_in[8];
    const float* b1         = (const float*)d_in[9];
    const float* W2         = (const float*)d_in[10];
    const float* b2         = (const float*)d_in[11];
    const float* W3         = (const float*)d_in[12];
    float* out = (float*)d_out;

    cudaFuncSetAttribute(pos_update_main,
                         cudaFuncAttributeMaxDynamicSharedMemorySize, SMEM_TOTAL);

    prep_w<<<128, 256>>>(Wd, bd, W1, b1, W2);
    prep_pq<<<256, 256>>>(x_emb);
    pos_update_main<<<2 * NODES, 512, SMEM_TOTAL>>>(pair_emb, coord_diff,
                                                    pair_mask, b2, W3);
    combine<<<(NODES * 3 + 511) / 512, 512>>>(pos, out);
    (void)in_sizes; (void)n_in; (void)out_size;
}

// round 12
// speedup vs baseline: 1.0928x; 1.0005x over previous
#include <cuda_runtime.h>
#include <cuda_fp16.h>
#include <cstdint>

#define BDIM 8
#define NDIM 256
#define HDIM 128
#define INDIM 259
#define NODES (BDIM * NDIM)   // 2048
#define NTILES (2 * NODES)    // 4096
#define GRID_MAIN 152         // persistent CTAs (GB300: 152 SMs)

// ---------------- device scratch ----------------
__device__ float g_P[NODES * HDIM];
__device__ __half g_Qh[NODES * HDIM];
__device__ float g_b1eff[HDIM];
__device__ __half g_Wf[HDIM * HDIM];                // W1c@Wd [h][k]
__device__ __half g_W2h[HDIM * HDIM];               // W2 [g][h]
__device__ float g_W1aT[HDIM * HDIM];
__device__ float g_W1bT[HDIM * HDIM];
__device__ float g_part[NTILES * 4 * 3];            // per (tile, wm-group) partials

// ---------------- helpers ----------------
__device__ __forceinline__ unsigned pack_h2(float lo, float hi) {
    unsigned r;
    asm("cvt.rn.f16x2.f32 %0, %1, %2;" : "=r"(r) : "f"(hi), "f"(lo));
    return r;
}
__device__ __forceinline__ unsigned silu2(float x0, float x1) {
    unsigned hx = pack_h2(x0, x1), hh, th, res;
    asm("mul.rn.f16x2 %0, %1, %2;" : "=r"(hh) : "r"(hx), "r"(0x38003800u));
    asm("tanh.approx.f16x2 %0, %1;" : "=r"(th) : "r"(hh));
    asm("fma.rn.f16x2 %0, %1, %2, %3;" : "=r"(res) : "r"(hh), "r"(th), "r"(hh));
    return res;
}
__device__ __forceinline__ uint32_t smem_u32(const void* p) {
    uint32_t a;
    asm("{ .reg .u64 t; cvta.to.shared.u64 t, %1; cvt.u32.u64 %0, t; }" : "=r"(a) : "l"(p));
    return a;
}

#define CP16(dst, src) \
    asm volatile("cp.async.cg.shared.global [%0], [%1], 16;" :: "r"(dst), "l"(src))
#define CP_COMMIT() asm volatile("cp.async.commit_group;")
#define CP_WAIT0()  asm volatile("cp.async.wait_group 0;")
#define BAR_GROUP(id) \
    asm volatile("bar.sync %0, 128;" :: "r"(id) : "memory")

// ---------------- prep_w ----------------
__global__ __launch_bounds__(256)
void prep_w(const float* __restrict__ Wd, const float* __restrict__ bd,
            const float* __restrict__ W1, const float* __restrict__ b1,
            const float* __restrict__ W2) {
    int h = blockIdx.x;
    int t = threadIdx.x;
    if (t < 128) {
        int k = t;
        float w1c0 = W1[h * INDIM + 2 * HDIM + 0];
        float w1c1 = W1[h * INDIM + 2 * HDIM + 1];
        float w1c2 = W1[h * INDIM + 2 * HDIM + 2];
        float v = w1c0 * Wd[k] + w1c1 * Wd[HDIM + k] + w1c2 * Wd[2 * HDIM + k];
        g_Wf[h * HDIM + k]  = __float2half_rn(v);
        g_W2h[h * HDIM + k] = __float2half_rn(W2[h * HDIM + k]);
        g_W1aT[k * HDIM + h] = W1[h * INDIM + k];
        if (k == 0)
            g_b1eff[h] = b1[h] + w1c0 * bd[0] + w1c1 * bd[1] + w1c2 * bd[2];
    } else {
        int k = t - 128;
        g_W1bT[k * HDIM + h] = W1[h * INDIM + HDIM + k];
    }
}

// ---------------- prep_pq ----------------
__global__ __launch_bounds__(256)
void prep_pq(const float* __restrict__ x_emb) {
    __shared__ float xs[8][HDIM];
    int t = threadIdx.x;
    int r0 = blockIdx.x * 8;
    for (int idx = t; idx < 8 * HDIM; idx += 256)
        xs[idx >> 7][idx & 127] = x_emb[r0 * HDIM + idx];
    __syncthreads();

    const int h = t & 127;
    const int n0 = (t >> 7) * 4;

    float p[4] = {0.f, 0.f, 0.f, 0.f};
    float q[4] = {0.f, 0.f, 0.f, 0.f};
#pragma unroll 4
    for (int k = 0; k < HDIM; k++) {
        float wa = g_W1aT[k * HDIM + h];
        float wb = g_W1bT[k * HDIM + h];
#pragma unroll
        for (int ii = 0; ii < 4; ii++) {
            float xv = xs[n0 + ii][k];
            p[ii] = fmaf(wa, xv, p[ii]);
            q[ii] = fmaf(wb, xv, q[ii]);
        }
    }
#pragma unroll
    for (int ii = 0; ii < 4; ii++) {
        g_P[(size_t)(r0 + n0 + ii) * HDIM + h]  = p[ii];
        g_Qh[(size_t)(r0 + n0 + ii) * HDIM + h] = __float2half_rn(q[ii]);
    }
}

// ---------------- main: persistent, group-pipelined ----------------
#define PA 136                 // smem pitch in f16
#define ROWB (PA * 2)          // 272 B

#define OFF_A     0            // 34816 (A/H1, group wm owns rows wm*32..+32)
#define OFF_B1    34816        // 34816
#define OFF_B2    69632        // 34816
#define OFF_BIASG 104448       // float[4][128] per-group P+b1eff
#define OFF_W3    106496       // float[128]
#define OFF_B2V   107008       // float[128]
#define OFF_B1E   107520       // float[128]
#define OFF_SRED  108032       // float[4][4][32]
#define SMEM_TOTAL 110080

#define LDSM_X4(r0, r1, r2, r3, addr) \
    asm volatile("ldmatrix.sync.aligned.m8n8.x4.shared.b16 {%0,%1,%2,%3}, [%4];" \
                 : "=r"(r0), "=r"(r1), "=r"(r2), "=r"(r3) : "r"(addr))

__device__ __forceinline__ void do_gemm(uint32_t aLane, uint32_t bLane,
                                        float acc[2][4][4]) {
#pragma unroll
    for (int ks = 0; ks < 8; ks++) {
        uint32_t a[2][4], b[4][2];
#pragma unroll
        for (int mt = 0; mt < 2; mt++)
            LDSM_X4(a[mt][0], a[mt][1], a[mt][2], a[mt][3],
                    aLane + mt * (16 * ROWB) + ks * 32);
#pragma unroll
        for (int np = 0; np < 2; np++)
            LDSM_X4(b[2 * np][0], b[2 * np][1], b[2 * np + 1][0], b[2 * np + 1][1],
                    bLane + np * (16 * ROWB) + ks * 32);
#pragma unroll
        for (int mt = 0; mt < 2; mt++)
#pragma unroll
            for (int nt = 0; nt < 4; nt++)
                asm volatile(
                    "mma.sync.aligned.m16n8k16.row.col.f32.f16.f16.f32 "
                    "{%0,%1,%2,%3}, {%4,%5,%6,%7}, {%8,%9}, {%0,%1,%2,%3};\n"
                    : "+f"(acc[mt][nt][0]), "+f"(acc[mt][nt][1]),
                      "+f"(acc[mt][nt][2]), "+f"(acc[mt][nt][3])
                    : "r"(a[mt][0]), "r"(a[mt][1]), "r"(a[mt][2]), "r"(a[mt][3]),
                      "r"(b[nt][0]), "r"(b[nt][1]));
    }
}

__global__ __launch_bounds__(512, 1)
void pos_update_main(const float* __restrict__ pair_emb,
                     const float* __restrict__ coord_diff,
                     const float* __restrict__ pair_mask,
                     const float* __restrict__ b2,
                     const float* __restrict__ W3) {
    extern __shared__ char smem[];
    __half* As   = reinterpret_cast<__half*>(smem + OFF_A);
    float* biasG = reinterpret_cast<float*>(smem + OFF_BIASG);  // [4][128]
    float* w3s   = reinterpret_cast<float*>(smem + OFF_W3);
    float* b2s   = reinterpret_cast<float*>(smem + OFF_B2V);
    float* b1s   = reinterpret_cast<float*>(smem + OFF_B1E);
    float* sRedG = reinterpret_cast<float*>(smem + OFF_SRED);   // [4][4][32]

    const uint32_t sb = smem_u32(smem);
    const int tid  = threadIdx.x;
    const int lane = tid & 31;
    const int warp = tid >> 5;
    const int wm = warp >> 2, wn = warp & 3;
    const int gt = tid & 127;                  // index within wm-group
    const int g = lane >> 2, l4 = lane & 3;

    const uint32_t aLane = sb + OFF_A + (uint32_t)(wm * 32 + (lane & 15)) * ROWB
                              + (uint32_t)(lane >> 4) * 16;
    const uint32_t bLane1 = sb + OFF_B1
        + (uint32_t)(wn * 32 + (lane & 7) + ((lane >> 4) << 3)) * ROWB
        + (uint32_t)((lane >> 3) & 1) * 16;
    const uint32_t bLane2 = bLane1 + (OFF_B2 - OFF_B1);

    // ---- one-time setup: weights + small vectors ----
    {
        const char* w1 = reinterpret_cast<const char*>(g_Wf);
        const char* w2 = reinterpret_cast<const char*>(g_W2h);
#pragma unroll
        for (int it = 0; it < 4; it++) {
            int idx = tid + it * 512;
            int r = idx >> 4, c = (idx & 15) << 3;
            uint32_t doff = (uint32_t)(r * PA + c) * 2;
            CP16(sb + OFF_B1 + doff, w1 + idx * 16);
            CP16(sb + OFF_B2 + doff, w2 + idx * 16);
        }
        CP_COMMIT();
        if (tid < 128) {
            w3s[tid] = W3[tid];
            b2s[tid] = b2[tid];
            b1s[tid] = g_b1eff[tid];
        }
        CP_WAIT0();
    }
    __syncthreads();

    // ---- prologue: prefetch A rows of first tile (this group's 32 rows) ----
    int tile = blockIdx.x;
    float4 Areg[8];
    {
        int blk = tile >> 1, j0 = (tile & 1) << 7;
        const float4* src = reinterpret_cast<const float4*>(
            pair_emb + ((size_t)blk * NDIM + j0 + wm * 32) * HDIM);
#pragma unroll
        for (int i = 0; i < 8; i++) Areg[i] = src[gt + i * 128];
    }

    unsigned qreg[2][4][2];
    float acc[2][4][4];

    for (; tile < NTILES; tile += GRID_MAIN) {
        const int blk = tile >> 1;
        const int j0 = (tile & 1) << 7;
        const int bbase = blk & ~255;

        // 1. store A(tile) f16 into this group's rows (overwrites old H1)
#pragma unroll
        for (int i = 0; i < 8; i++) {
            int idx = gt + i * 128;
            int r = wm * 32 + (idx >> 5);
            int c = (idx & 31) << 2;
            uint2 v;
            v.x = pack_h2(Areg[i].x, Areg[i].y);
            v.y = pack_h2(Areg[i].z, Areg[i].w);
            *reinterpret_cast<uint2*>(As + r * PA + c) = v;
        }
        // 2. per-group bias staging: P[blk] + b1eff
        biasG[wm * 128 + gt] = g_P[(size_t)blk * HDIM + gt] + b1s[gt];
        BAR_GROUP(1 + wm);

        // 3. prefetch A(next tile) and Q(this tile) into registers
        {
            int ntile = tile + GRID_MAIN;
            if (ntile < NTILES) {
                int nblk = ntile >> 1, nj0 = (ntile & 1) << 7;
                const float4* src = reinterpret_cast<const float4*>(
                    pair_emb + ((size_t)nblk * NDIM + nj0 + wm * 32) * HDIM);
#pragma unroll
                for (int i = 0; i < 8; i++) Areg[i] = src[gt + i * 128];
            }
#pragma unroll
            for (int mt = 0; mt < 2; mt++) {
                const __half* qrow = g_Qh +
                    (size_t)(bbase + j0 + wm * 32 + mt * 16 + g) * HDIM;
#pragma unroll
                for (int nt = 0; nt < 4; nt++) {
                    int c = wn * 32 + nt * 8 + l4 * 2;
                    qreg[mt][nt][0] = *reinterpret_cast<const unsigned*>(qrow + c);
                    qreg[mt][nt][1] = *reinterpret_cast<const unsigned*>(qrow + 8 * HDIM + c);
                }
            }
        }

        // 4. GEMM1
#pragma unroll
        for (int mt = 0; mt < 2; mt++)
#pragma unroll
            for (int nt = 0; nt < 4; nt++)
#pragma unroll
                for (int e = 0; e < 4; e++) acc[mt][nt][e] = 0.f;
        do_gemm(aLane, bLane1, acc);
        BAR_GROUP(1 + wm);

        // 5. epilogue 1: silu(acc + biasG + Q) -> H1 f16 over A rows
#pragma unroll
        for (int mt = 0; mt < 2; mt++) {
            int r = wm * 32 + mt * 16 + g;
#pragma unroll
            for (int nt = 0; nt < 4; nt++) {
                int c = wn * 32 + nt * 8 + l4 * 2;
                float2 ql = __half22float2(*reinterpret_cast<__half2*>(&qreg[mt][nt][0]));
                float2 qh = __half22float2(*reinterpret_cast<__half2*>(&qreg[mt][nt][1]));
                float bc0 = biasG[wm * 128 + c], bc1 = biasG[wm * 128 + c + 1];
                float x0 = acc[mt][nt][0] + bc0 + ql.x;
                float x1 = acc[mt][nt][1] + bc1 + ql.y;
                float x2 = acc[mt][nt][2] + bc0 + qh.x;
                float x3 = acc[mt][nt][3] + bc1 + qh.y;
                *reinterpret_cast<unsigned*>(As + r * PA + c)       = silu2(x0, x1);
                *reinterpret_cast<unsigned*>(As + (r + 8) * PA + c) = silu2(x2, x3);
            }
        }
        BAR_GROUP(1 + wm);

        // 6. GEMM2
#pragma unroll
        for (int mt = 0; mt < 2; mt++)
#pragma unroll
            for (int nt = 0; nt < 4; nt++)
#pragma unroll
                for (int e = 0; e < 4; e++) acc[mt][nt][e] = 0.f;
        do_gemm(aLane, bLane2, acc);

        // 7. epilogue 2: silu, dot W3, per-(group,warp) slice to smem
        float sAcc[2][2] = {{0.f, 0.f}, {0.f, 0.f}};
#pragma unroll
        for (int mt = 0; mt < 2; mt++) {
#pragma unroll
            for (int nt = 0; nt < 4; nt++) {
                int c = wn * 32 + nt * 8 + l4 * 2;
                float bb0 = b2s[c], bb1 = b2s[c + 1];
                float w30 = w3s[c], w31 = w3s[c + 1];
                unsigned ylo = silu2(acc[mt][nt][0] + bb0, acc[mt][nt][1] + bb1);
                unsigned yhi = silu2(acc[mt][nt][2] + bb0, acc[mt][nt][3] + bb1);
                float2 y01 = __half22float2(*reinterpret_cast<__half2*>(&ylo));
                float2 y23 = __half22float2(*reinterpret_cast<__half2*>(&yhi));
                sAcc[mt][0] += y01.x * w30 + y01.y * w31;
                sAcc[mt][1] += y23.x * w30 + y23.y * w31;
            }
        }
#pragma unroll
        for (int mt = 0; mt < 2; mt++)
#pragma unroll
            for (int hh = 0; hh < 2; hh++) {
                sAcc[mt][hh] += __shfl_xor_sync(0xffffffffu, sAcc[mt][hh], 1);
                sAcc[mt][hh] += __shfl_xor_sync(0xffffffffu, sAcc[mt][hh], 2);
            }
        if (l4 == 0) {
#pragma unroll
            for (int mt = 0; mt < 2; mt++) {
                sRedG[(wm * 4 + wn) * 32 + mt * 16 + g]     = sAcc[mt][0];
                sRedG[(wm * 4 + wn) * 32 + mt * 16 + 8 + g] = sAcc[mt][1];
            }
        }
        BAR_GROUP(1 + wm);

        // 8. group-local final reduce (warp wn==0 of the group)
        if (wn == 0) {
            int r = lane;
            size_t jj = (size_t)blk * NDIM + j0 + wm * 32 + r;
            float s = sRedG[(wm * 4 + 0) * 32 + r] + sRedG[(wm * 4 + 1) * 32 + r]
                    + sRedG[(wm * 4 + 2) * 32 + r] + sRedG[(wm * 4 + 3) * 32 + r];
            float sj = s * pair_mask[jj];
            const float* cd = coord_diff + jj * 3;
            float t0 = cd[0] * sj, t1 = cd[1] * sj, t2 = cd[2] * sj;
#pragma unroll
            for (int off = 16; off > 0; off >>= 1) {
                t0 += __shfl_down_sync(0xffffffffu, t0, off);
                t1 += __shfl_down_sync(0xffffffffu, t1, off);
                t2 += __shfl_down_sync(0xffffffffu, t2, off);
            }
            if (lane == 0) {
                float* gp = g_part + ((size_t)tile * 4 + wm) * 3;
                gp[0] = t0; gp[1] = t1; gp[2] = t2;
            }
        }
    }
}

// ---------------- combine kernel ----------------
__global__ void combine(const float* __restrict__ pos, float* __restrict__ out) {
    int i = blockIdx.x * blockDim.x + threadIdx.x;   // 0..6143
    if (i < NODES * 3) {
        int node = i / 3, d = i - node * 3;
        float s = 0.f;
#pragma unroll
        for (int half = 0; half < 2; half++)
#pragma unroll
            for (int wmg = 0; wmg < 4; wmg++)
                s += g_part[(((size_t)(node * 2 + half) * 4) + wmg) * 3 + d];
        out[i] = pos[i] + s;
    }
}

// ---------------- launcher ----------------
extern "C" void kernel_launch(void* const* d_in, const int* in_sizes, int n_in,
                              void* d_out, int out_size) {
    const float* x_emb      = (const float*)d_in[0];
    const float* pair_emb   = (const float*)d_in[1];
    const float* pos        = (const float*)d_in[2];
    const float* coord_diff = (const float*)d_in[3];
    const float* pair_mask  = (const float*)d_in[5];
    const float* Wd         = (const float*)d_in[6];
    const float* bd         = (const float*)d_in[7];
    const float* W1         = (const float*)d_in[8];
    const float* b1         = (const float*)d_in[9];
    const float* W2         = (const float*)d_in[10];
    const float* b2         = (const float*)d_in[11];
    const float* W3         = (const float*)d_in[12];
    float* out = (float*)d_out;

    cudaFuncSetAttribute(pos_update_main,
                         cudaFuncAttributeMaxDynamicSharedMemorySize, SMEM_TOTAL);

    prep_w<<<128, 256>>>(Wd, bd, W1, b1, W2);
    prep_pq<<<256, 256>>>(x_emb);
    pos_update_main<<<GRID_MAIN, 512, SMEM_TOTAL>>>(pair_emb, coord_diff,
                                                    pair_mask, b2, W3);
    combine<<<(NODES * 3 + 511) / 512, 512>>>(pos, out);
    (void)in_sizes; (void)n_in; (void)out_size;
}